// round 14
// baseline (speedup 1.0000x reference)
#include <cuda_runtime.h>
#include <cuda_bf16.h>
#include <cuda_fp16.h>
#include <cstdint>

#define BB 4
#define CC 2048
#define NN 2304   // 48*48
#define DD 256

typedef __nv_bfloat16 bf16;
typedef __nv_bfloat162 bf162;

// ---------------------------------------------------------------------------
// Scratch (__device__ globals)
// ---------------------------------------------------------------------------
__device__ bf16 g_xh[2ull * BB * NN * CC];
__device__ bf16 g_xl[2ull * BB * NN * CC];
__device__ bf16 g_wh[2ull * DD * CC];
__device__ bf16 g_wl[2ull * DD * CC];
__device__ bf16 g_qh[2ull * BB * NN * DD];
__device__ bf16 g_ql[2ull * BB * NN * DD];
__device__ bf16 g_kh[2ull * BB * NN * DD];
__device__ bf16 g_kl[2ull * BB * NN * DD];
__device__ float g_attn[2ull * BB * NN * NN];    // fp32 scores
__device__ __half g_attn_h[2ull * BB * NN * NN]; // fp16 softmaxed attn
__device__ __half g_vh[2ull * BB * CC * NN];     // fp16 copies of L (src 0) and R (src 1)

// ---------------------------------------------------------------------------
// helpers
// ---------------------------------------------------------------------------
__device__ __forceinline__ uint32_t smem_u32(const void* p) {
    uint32_t a;
    asm("{ .reg .u64 t; cvta.to.shared.u64 t, %1; cvt.u32.u64 %0, t; }" : "=r"(a) : "l"(p));
    return a;
}

__device__ __forceinline__ void cp16(uint32_t dst, const void* src) {
    asm volatile("cp.async.cg.shared.global [%0], [%1], 16;" :: "r"(dst), "l"(src));
}
#define CP_COMMIT() asm volatile("cp.async.commit_group;")
#define CP_WAIT(n)  asm volatile("cp.async.wait_group %0;" :: "n"(n))

__device__ __forceinline__ void ldsm4(uint32_t* r, uint32_t addr) {
    asm volatile("ldmatrix.sync.aligned.m8n8.x4.shared.b16 {%0,%1,%2,%3}, [%4];"
        : "=r"(r[0]), "=r"(r[1]), "=r"(r[2]), "=r"(r[3]) : "r"(addr));
}

__device__ __forceinline__ void mma16(float* c, const uint32_t* a, const uint32_t* b) {
    asm volatile(
        "mma.sync.aligned.m16n8k16.row.col.f32.bf16.bf16.f32 "
        "{%0,%1,%2,%3}, {%4,%5,%6,%7}, {%8,%9}, {%0,%1,%2,%3};"
        : "+f"(c[0]), "+f"(c[1]), "+f"(c[2]), "+f"(c[3])
        : "r"(a[0]), "r"(a[1]), "r"(a[2]), "r"(a[3]), "r"(b[0]), "r"(b[1]));
}

__device__ __forceinline__ void mma16h(float* c, const uint32_t* a, const uint32_t* b) {
    asm volatile(
        "mma.sync.aligned.m16n8k16.row.col.f32.f16.f16.f32 "
        "{%0,%1,%2,%3}, {%4,%5,%6,%7}, {%8,%9}, {%0,%1,%2,%3};"
        : "+f"(c[0]), "+f"(c[1]), "+f"(c[2]), "+f"(c[3])
        : "r"(a[0]), "r"(a[1]), "r"(a[2]), "r"(a[3]), "r"(b[0]), "r"(b[1]));
}

__device__ __forceinline__ void split_bf(float v, bf16& h, bf16& l) {
    h = __float2bfloat16(v);
    l = __float2bfloat16(v - __bfloat162float(h));
}

// fast exp: exp2 poly (deg-6, rel err ~1.5e-5), no MUFU
__device__ __forceinline__ float fexp(float x) {
    float t = fmaxf(x * 1.44269504089f, -120.f);
    float fi = floorf(t);
    float f = t - fi;
    float p = 1.54953e-4f;
    p = fmaf(p, f, 0.00133335581f);
    p = fmaf(p, f, 0.00961812911f);
    p = fmaf(p, f, 0.0555041087f);
    p = fmaf(p, f, 0.240226507f);
    p = fmaf(p, f, 0.693147181f);
    p = fmaf(p, f, 1.0f);
    return __int_as_float(__float_as_int(p) + ((int)fi << 23));
}

// ===========================================================================
// split_w (unchanged)
// ===========================================================================
__global__ void __launch_bounds__(256) split_w_kernel(
    const float* __restrict__ wq, const float* __restrict__ wr,
    bf16* __restrict__ wh, bf16* __restrict__ wl)
{
    const size_t total2 = (size_t)2 * DD * CC / 2;
    size_t i = (size_t)blockIdx.x * 256 + threadIdx.x;
    if (i >= total2) return;
    size_t p = i * 2;
    const float* src = (p < (size_t)DD * CC) ? wq + p : wr + (p - (size_t)DD * CC);
    float2 v = *(const float2*)src;
    bf16 h0, l0, h1, l1;
    split_bf(v.x, h0, l0);
    split_bf(v.y, h1, l1);
    *(bf162*)&wh[p] = bf162(h0, h1);
    *(bf162*)&wl[p] = bf162(l0, l1);
}

// ===========================================================================
// prep: fused conv_copy + split_x, vectorized (unchanged from R13)
// ===========================================================================
__global__ void __launch_bounds__(256) prep_kernel(
    const float* __restrict__ L, const float* __restrict__ R,
    float* __restrict__ out, __half* __restrict__ vh,
    bf16* __restrict__ xh, bf16* __restrict__ xl)
{
    __shared__ float t[64][65];
    const int z = blockIdx.z, src = z >> 2, b = z & 3;
    const float* X = (src ? R : L) + (size_t)b * CC * NN;
    float* outp = out + (src ? (size_t)BB * 2 * CC * NN : 0) + (size_t)b * 2 * CC * NN;
    __half* vp = vh + (size_t)z * CC * NN;
    bf16* oh = xh + (size_t)z * NN * CC;
    bf16* ol = xl + (size_t)z * NN * CC;
    const int n0 = blockIdx.x << 6, c0 = blockIdx.y << 6;
    const int tid = threadIdx.x;

#pragma unroll
    for (int i = 0; i < 4; i++) {
        int idx = tid + (i << 8);
        int cc = idx >> 4;
        int n4 = (idx & 15) << 2;
        size_t go = (size_t)(c0 + cc) * NN + n0 + n4;
        float4 v = *(const float4*)(X + go);
        *(float4*)(outp + go) = v;
        union { __half2 h2[2]; uint2 u; } pv;
        pv.h2[0] = __floats2half2_rn(v.x, v.y);
        pv.h2[1] = __floats2half2_rn(v.z, v.w);
        *(uint2*)(vp + go) = pv.u;
        t[cc][n4 + 0] = v.x;
        t[cc][n4 + 1] = v.y;
        t[cc][n4 + 2] = v.z;
        t[cc][n4 + 3] = v.w;
    }
    __syncthreads();

    {
        const int n = tid >> 2;
        const int cg = (tid & 3) << 4;
        union { bf162 h2[8]; uint4 u4[2]; } ph, pl;
#pragma unroll
        for (int e = 0; e < 8; e++) {
            float v0 = t[cg + 2 * e][n], v1 = t[cg + 2 * e + 1][n];
            bf16 h0, l0, h1, l1;
            split_bf(v0, h0, l0);
            split_bf(v1, h1, l1);
            ph.h2[e] = bf162(h0, h1);
            pl.h2[e] = bf162(l0, l1);
        }
        size_t off = (size_t)(n0 + n) * CC + c0 + cg;
        *(uint4*)&oh[off]     = ph.u4[0];
        *(uint4*)&oh[off + 8] = ph.u4[1];
        *(uint4*)&ol[off]     = pl.u4[0];
        *(uint4*)&ol[off + 8] = pl.u4[1];
    }
}

// ===========================================================================
// proj (bf16x3, ldmatrix + swizzle, 2 CTAs/SM, unchanged from R12)
// ===========================================================================
#define PR_STAGE_B 32768

__global__ void __launch_bounds__(256, 2) proj_bf16_kernel(
    const bf16* __restrict__ xh, const bf16* __restrict__ xl,
    const bf16* __restrict__ whg, const bf16* __restrict__ wlg,
    const float* __restrict__ bq, const float* __restrict__ br,
    bf16* __restrict__ qh_g, bf16* __restrict__ ql_g,
    bf16* __restrict__ kh_g, bf16* __restrict__ kl_g)
{
    extern __shared__ char prsm[];
    const int x = blockIdx.x >> 1;
    const int d0 = (blockIdx.x & 1) << 7;
    const int z = blockIdx.z, src = z >> 2, b = z & 3;
    const bf16* Xh = xh + (size_t)z * NN * CC;
    const bf16* Xl = xl + (size_t)z * NN * CC;
    const bf16* Wh = whg + (size_t)x * DD * CC + (size_t)d0 * CC;
    const bf16* Wl = wlg + (size_t)x * DD * CC + (size_t)d0 * CC;
    const float* bias = x ? br : bq;
    const int dir = x ? (src ^ 1) : src;
    bf16* oh = (x ? kh_g : qh_g) + ((size_t)dir * BB + b) * NN * DD;
    bf16* ol = (x ? kl_g : ql_g) + ((size_t)dir * BB + b) * NN * DD;
    const int m0 = blockIdx.y << 7;

    const uint32_t ab = (smem_u32(prsm) + 127) & ~127u;

    const int tid = threadIdx.x, wid = tid >> 5, lane = tid & 31;
    const int wm = wid >> 1, wn = wid & 1;
    const int gid = lane >> 2, tig = lane & 3;
    const int li = lane >> 3, lj = lane & 7;
    const int swj = lj >> 1;

    float acc[2][8][4];
#pragma unroll
    for (int i = 0; i < 2; i++)
#pragma unroll
        for (int j = 0; j < 8; j++)
#pragma unroll
            for (int e = 0; e < 4; e++) acc[i][j][e] = 0.f;

    auto load_tile = [&](int s, int kt) {
        const uint32_t st = ab + (uint32_t)s * PR_STAGE_B;
        const int kb = kt << 5;
#pragma unroll
        for (int i = 0; i < 2; i++) {
            int idx = tid + (i << 8);
            int row = idx >> 2, g = idx & 3;
            uint32_t off = row * 64 + 16 * (g ^ ((row >> 1) & 3));
            cp16(st + off,         Xh + (size_t)(m0 + row) * CC + kb + g * 8);
            cp16(st + 8192 + off,  Xl + (size_t)(m0 + row) * CC + kb + g * 8);
            cp16(st + 16384 + off, Wh + (size_t)row * CC + kb + g * 8);
            cp16(st + 24576 + off, Wl + (size_t)row * CC + kb + g * 8);
        }
    };

    auto compute = [&](int s) {
        const uint32_t st = ab + (uint32_t)s * PR_STAGE_B;
        const uint32_t a_rb = ((wm << 5) + ((li & 1) << 3) + lj) * 64;
        const uint32_t b_rb = ((wn << 6) + ((li >> 1) << 3) + lj) * 64;
#pragma unroll
        for (int ks = 0; ks < 2; ks++) {
            const uint32_t xa = 16u * (((ks << 1) + (li >> 1)) ^ swj);
            const uint32_t xb = 16u * (((ks << 1) + (li & 1)) ^ swj);
            uint32_t ah[2][4], al[2][4];
#pragma unroll
            for (int mf = 0; mf < 2; mf++) {
                ldsm4(ah[mf], st + a_rb + mf * 1024 + xa);
                ldsm4(al[mf], st + 8192 + a_rb + mf * 1024 + xa);
            }
            uint32_t bh[4][4], bl[4][4];
#pragma unroll
            for (int nf2 = 0; nf2 < 4; nf2++) {
                ldsm4(bh[nf2], st + 16384 + b_rb + nf2 * 1024 + xb);
                ldsm4(bl[nf2], st + 24576 + b_rb + nf2 * 1024 + xb);
            }
#pragma unroll
            for (int mf = 0; mf < 2; mf++)
#pragma unroll
                for (int nf2 = 0; nf2 < 4; nf2++) {
                    mma16(acc[mf][2 * nf2],     ah[mf], &bh[nf2][0]);
                    mma16(acc[mf][2 * nf2],     ah[mf], &bl[nf2][0]);
                    mma16(acc[mf][2 * nf2],     al[mf], &bh[nf2][0]);
                    mma16(acc[mf][2 * nf2 + 1], ah[mf], &bh[nf2][2]);
                    mma16(acc[mf][2 * nf2 + 1], ah[mf], &bl[nf2][2]);
                    mma16(acc[mf][2 * nf2 + 1], al[mf], &bh[nf2][2]);
                }
        }
    };

    const int KT = CC >> 5;  // 64
    load_tile(0, 0); CP_COMMIT();
    load_tile(1, 1); CP_COMMIT();
    for (int kt = 0; kt < KT; kt++) {
        CP_WAIT(1);
        __syncthreads();
        compute(kt % 3);
        if (kt + 2 < KT) load_tile((kt + 2) % 3, kt + 2);
        CP_COMMIT();
    }

#pragma unroll
    for (int mf = 0; mf < 2; mf++) {
        const int r = m0 + (wm << 5) + (mf << 4) + gid;
#pragma unroll
        for (int nf = 0; nf < 8; nf++) {
            const int col = d0 + (wn << 6) + (nf << 3) + (tig << 1);
            const float b0 = bias[col], b1 = bias[col + 1];
            float v0 = acc[mf][nf][0] + b0, v1 = acc[mf][nf][1] + b1;
            float v2 = acc[mf][nf][2] + b0, v3 = acc[mf][nf][3] + b1;
            bf16 h0, l0, h1, l1, h2, l2, h3, l3;
            split_bf(v0, h0, l0); split_bf(v1, h1, l1);
            split_bf(v2, h2, l2); split_bf(v3, h3, l3);
            *(bf162*)&oh[(size_t)r * DD + col]       = bf162(h0, h1);
            *(bf162*)&oh[(size_t)(r + 8) * DD + col] = bf162(h2, h3);
            *(bf162*)&ol[(size_t)r * DD + col]       = bf162(l0, l1);
            *(bf162*)&ol[(size_t)(r + 8) * DD + col] = bf162(l2, l3);
        }
    }
}

// ===========================================================================
// scores: persistent CTAs, continuous 3-stage ring across tiles (bf16x3)
// CTA 128x128, 256 threads, 2 CTAs/SM. Tiles: 18j x 18i x 8z = 2592.
// ===========================================================================
#define SC_STAGE_B 32768
#define SC_NT 2592

__global__ void __launch_bounds__(256, 2) scores_bf16_kernel(
    const bf16* __restrict__ qh_g, const bf16* __restrict__ ql_g,
    const bf16* __restrict__ kh_g, const bf16* __restrict__ kl_g,
    float* __restrict__ Sb)
{
    extern __shared__ char scsm[];
    const uint32_t ab = (smem_u32(scsm) + 127) & ~127u;
    const int bid = blockIdx.x, stride = gridDim.x;

    const int tid = threadIdx.x, wid = tid >> 5, lane = tid & 31;
    const int wm = wid >> 1, wn = wid & 1;
    const int gid = lane >> 2, tig = lane & 3;
    const int li = lane >> 3, lj = lane & 7;
    const int swj = lj >> 1;

    float acc[2][8][4];
#pragma unroll
    for (int i = 0; i < 2; i++)
#pragma unroll
        for (int j = 0; j < 8; j++)
#pragma unroll
            for (int e = 0; e < 4; e++) acc[i][j][e] = 0.f;

    // ---- load-side state ----
    int lt = bid, lk = 0;
    const bf16 *Lq = nullptr, *Lql = nullptr, *Lk = nullptr, *Lkl = nullptr;

    auto set_bases = [&](int t) {
        int z = t / 324;
        int r = t - z * 324;
        int it = r / 18;
        int jt = r - it * 18;
        size_t zo = (size_t)z * NN * DD;
        size_t io = (size_t)(it << 7) * DD, jo = (size_t)(jt << 7) * DD;
        Lq  = qh_g + zo + io;
        Lql = ql_g + zo + io;
        Lk  = kh_g + zo + jo;
        Lkl = kl_g + zo + jo;
    };
    if (lt < SC_NT) set_bases(lt);

    auto load_stage = [&](int s) {
        if (lt < SC_NT) {
            const uint32_t st = ab + (uint32_t)s * SC_STAGE_B;
            const int kb = lk << 5;
#pragma unroll
            for (int i = 0; i < 2; i++) {
                int idx = tid + (i << 8);
                int row = idx >> 2, g = idx & 3;
                uint32_t off = row * 64 + 16 * (g ^ ((row >> 1) & 3));
                cp16(st + off,         Lq  + (size_t)row * DD + kb + g * 8);
                cp16(st + 8192 + off,  Lql + (size_t)row * DD + kb + g * 8);
                cp16(st + 16384 + off, Lk  + (size_t)row * DD + kb + g * 8);
                cp16(st + 24576 + off, Lkl + (size_t)row * DD + kb + g * 8);
            }
            if (++lk == 8) {
                lk = 0;
                lt += stride;
                if (lt < SC_NT) set_bases(lt);
            }
        }
        CP_COMMIT();
    };

    auto compute = [&](int s) {
        const uint32_t st = ab + (uint32_t)s * SC_STAGE_B;
        const uint32_t a_rb = ((wm << 5) + ((li & 1) << 3) + lj) * 64;
        const uint32_t b_rb = ((wn << 6) + ((li >> 1) << 3) + lj) * 64;
#pragma unroll
        for (int ks = 0; ks < 2; ks++) {
            const uint32_t xa = 16u * (((ks << 1) + (li >> 1)) ^ swj);
            const uint32_t xb = 16u * (((ks << 1) + (li & 1)) ^ swj);
            uint32_t ah[2][4], al[2][4];
#pragma unroll
            for (int mf = 0; mf < 2; mf++) {
                ldsm4(ah[mf], st + a_rb + mf * 1024 + xa);
                ldsm4(al[mf], st + 8192 + a_rb + mf * 1024 + xa);
            }
            uint32_t bh[4][4], bl[4][4];
#pragma unroll
            for (int nf2 = 0; nf2 < 4; nf2++) {
                ldsm4(bh[nf2], st + 16384 + b_rb + nf2 * 1024 + xb);
                ldsm4(bl[nf2], st + 24576 + b_rb + nf2 * 1024 + xb);
            }
#pragma unroll
            for (int mf = 0; mf < 2; mf++)
#pragma unroll
                for (int nf2 = 0; nf2 < 4; nf2++) {
                    mma16(acc[mf][2 * nf2],     ah[mf], &bh[nf2][0]);
                    mma16(acc[mf][2 * nf2],     ah[mf], &bl[nf2][0]);
                    mma16(acc[mf][2 * nf2],     al[mf], &bh[nf2][0]);
                    mma16(acc[mf][2 * nf2 + 1], ah[mf], &bh[nf2][2]);
                    mma16(acc[mf][2 * nf2 + 1], ah[mf], &bl[nf2][2]);
                    mma16(acc[mf][2 * nf2 + 1], al[mf], &bh[nf2][2]);
                }
        }
    };

    // ---- persistent mainloop ----
    load_stage(0);
    load_stage(1);
    int scmp = 0;
#pragma unroll 1
    for (int ct = bid; ct < SC_NT; ct += stride) {
#pragma unroll 1
        for (int ck = 0; ck < 8; ck++) {
            CP_WAIT(1);
            __syncthreads();
            compute(scmp);
            if (++scmp == 3) scmp = 0;
            int sl = scmp + 1; if (sl == 3) sl = 0;
            load_stage(sl);
        }
        // epilogue for tile ct
        {
            int z = ct / 324;
            int r = ct - z * 324;
            int it = r / 18;
            int jt = r - it * 18;
            float* S = Sb + (size_t)z * NN * NN;
            const int i0 = it << 7, j0 = jt << 7;
#pragma unroll
            for (int mf = 0; mf < 2; mf++) {
                const int rr = i0 + (wm << 5) + (mf << 4) + gid;
#pragma unroll
                for (int nf = 0; nf < 8; nf++) {
                    const int col = j0 + (wn << 6) + (nf << 3) + (tig << 1);
                    *(float2*)&S[(size_t)rr * NN + col]       = make_float2(acc[mf][nf][0], acc[mf][nf][1]);
                    *(float2*)&S[(size_t)(rr + 8) * NN + col] = make_float2(acc[mf][nf][2], acc[mf][nf][3]);
                    acc[mf][nf][0] = 0.f; acc[mf][nf][1] = 0.f;
                    acc[mf][nf][2] = 0.f; acc[mf][nf][3] = 0.f;
                }
            }
        }
    }
}

// ===========================================================================
// av: persistent CTAs, continuous ring (fp16). Tiles: 18n x 16c x 8z = 2304,
// KT=36 per tile. CTA 128x128, 256 threads, 2 CTAs/SM.
// ===========================================================================
#define AV_STAGE_B 32768
#define AV_NT 2304
#define AV_KT 36

__global__ void __launch_bounds__(256, 2) av_fp16_kernel(
    const __half* __restrict__ vhg, const __half* __restrict__ attnb,
    float* __restrict__ out)
{
    extern __shared__ char avsm[];
    const uint32_t ab = (smem_u32(avsm) + 127) & ~127u;
    const int bid = blockIdx.x, stride = gridDim.x;

    const int tid = threadIdx.x, wid = tid >> 5, lane = tid & 31;
    const int wm = wid >> 1, wn = wid & 1;
    const int gid = lane >> 2, tig = lane & 3;
    const int li = lane >> 3, lj = lane & 7;

    float acc[2][8][4];
#pragma unroll
    for (int i = 0; i < 2; i++)
#pragma unroll
        for (int j = 0; j < 8; j++)
#pragma unroll
            for (int e = 0; e < 4; e++) acc[i][j][e] = 0.f;

    // ---- load-side state ----
    int lt = bid, lk = 0;
    const __half *LV = nullptr, *LA = nullptr;

    auto set_bases = [&](int t) {
        int z = t / 288;
        int r = t - z * 288;
        int ctile = r / 18;
        int ntile = r - ctile * 18;
        const int dir = z >> 2, b = z & 3;
        LV = vhg + ((size_t)((dir ^ 1) * BB + b)) * CC * NN + (size_t)(ctile << 7) * NN;
        LA = attnb + (size_t)z * NN * NN + (size_t)(ntile << 7) * NN;
    };
    if (lt < AV_NT) set_bases(lt);

    auto load_stage = [&](int s) {
        if (lt < AV_NT) {
            const uint32_t st = ab + (uint32_t)s * AV_STAGE_B;
            const int kb = lk << 6;
#pragma unroll
            for (int i = 0; i < 4; i++) {
                int idx = tid + (i << 8);
                int row = idx >> 3, g = idx & 7;
                uint32_t off = row * 128 + 16 * (g ^ (row & 7));
                cp16(st + off,         LV + (size_t)row * NN + kb + g * 8);
                cp16(st + 16384 + off, LA + (size_t)row * NN + kb + g * 8);
            }
            if (++lk == AV_KT) {
                lk = 0;
                lt += stride;
                if (lt < AV_NT) set_bases(lt);
            }
        }
        CP_COMMIT();
    };

    const uint32_t a_rb = ((wm << 5) + ((li & 1) << 3) + lj) * 128;
    const uint32_t b_rb = ((wn << 6) + ((li >> 1) << 3) + lj) * 128;

    auto compute = [&](int s) {
        const uint32_t st = ab + (uint32_t)s * AV_STAGE_B;
#pragma unroll
        for (int ks = 0; ks < 4; ks++) {   // 4 x k16 = k64
            const uint32_t xa = 16u * (((ks << 1) + (li >> 1)) ^ lj);
            const uint32_t xb = 16u * (((ks << 1) + (li & 1)) ^ lj);
            uint32_t a[2][4];
#pragma unroll
            for (int mf = 0; mf < 2; mf++)
                ldsm4(a[mf], st + a_rb + mf * 2048 + xa);
            uint32_t bf[4][4];
#pragma unroll
            for (int nf2 = 0; nf2 < 4; nf2++)
                ldsm4(bf[nf2], st + 16384 + b_rb + nf2 * 2048 + xb);
#pragma unroll
            for (int mf = 0; mf < 2; mf++)
#pragma unroll
                for (int nf2 = 0; nf2 < 4; nf2++) {
                    mma16h(acc[mf][2 * nf2],     a[mf], &bf[nf2][0]);
                    mma16h(acc[mf][2 * nf2 + 1], a[mf], &bf[nf2][2]);
                }
        }
    };

    // ---- persistent mainloop ----
    load_stage(0);
    load_stage(1);
    int scmp = 0;
#pragma unroll 1
    for (int ct = bid; ct < AV_NT; ct += stride) {
#pragma unroll 1
        for (int ck = 0; ck < AV_KT; ck++) {
            CP_WAIT(1);
            __syncthreads();
            compute(scmp);
            if (++scmp == 3) scmp = 0;
            int sl = scmp + 1; if (sl == 3) sl = 0;
            load_stage(sl);
        }
        // epilogue for tile ct
        {
            int z = ct / 288;
            int r = ct - z * 288;
            int ctile = r / 18;
            int ntile = r - ctile * 18;
            const int dir = z >> 2, b = z & 3;
            float* outb = out + ((size_t)(dir ? BB : 0) + b) * 2 * CC * NN + (size_t)CC * NN;
            const int c0r = ctile << 7, n0 = ntile << 7;
#pragma unroll
            for (int mf = 0; mf < 2; mf++) {
                const int rr = c0r + (wm << 5) + (mf << 4) + gid;
#pragma unroll
                for (int nf = 0; nf < 8; nf++) {
                    const int col = n0 + (wn << 6) + (nf << 3) + (tig << 1);
                    *(float2*)&outb[(size_t)rr * NN + col]       = make_float2(acc[mf][nf][0], acc[mf][nf][1]);
                    *(float2*)&outb[(size_t)(rr + 8) * NN + col] = make_float2(acc[mf][nf][2], acc[mf][nf][3]);
                    acc[mf][nf][0] = 0.f; acc[mf][nf][1] = 0.f;
                    acc[mf][nf][2] = 0.f; acc[mf][nf][3] = 0.f;
                }
            }
        }
    }
}

// ===========================================================================
// softmax: reads fp32 scores, writes fp16 attn (unchanged)
// ===========================================================================
__global__ void __launch_bounds__(288) softmax_kernel(
    const float* __restrict__ Sb, __half* __restrict__ Ob)
{
    const float4* S4 = (const float4*)(Sb + (size_t)blockIdx.x * NN);
    __half* O = Ob + (size_t)blockIdx.x * NN;
    const int tid = threadIdx.x;
    __shared__ float red[9];
    __shared__ float bcast;

    float4 va = S4[tid], vb = S4[tid + 288];
    float m = fmaxf(fmaxf(fmaxf(va.x, va.y), fmaxf(va.z, va.w)),
                    fmaxf(fmaxf(vb.x, vb.y), fmaxf(vb.z, vb.w)));
#pragma unroll
    for (int o = 16; o; o >>= 1) m = fmaxf(m, __shfl_xor_sync(0xffffffffu, m, o));
    if ((tid & 31) == 0) red[tid >> 5] = m;
    __syncthreads();
    if (tid == 0) {
        float t = red[0];
#pragma unroll
        for (int i = 1; i < 9; i++) t = fmaxf(t, red[i]);
        bcast = t;
    }
    __syncthreads();
    m = bcast;

    va.x = fexp(va.x - m); va.y = fexp(va.y - m);
    va.z = fexp(va.z - m); va.w = fexp(va.w - m);
    vb.x = fexp(vb.x - m); vb.y = fexp(vb.y - m);
    vb.z = fexp(vb.z - m); vb.w = fexp(vb.w - m);
    float s = va.x + va.y + va.z + va.w + vb.x + vb.y + vb.z + vb.w;
#pragma unroll
    for (int o = 16; o; o >>= 1) s += __shfl_xor_sync(0xffffffffu, s, o);
    __syncthreads();
    if ((tid & 31) == 0) red[tid >> 5] = s;
    __syncthreads();
    if (tid == 0) {
        float t = 0.f;
#pragma unroll
        for (int i = 0; i < 9; i++) t += red[i];
        bcast = 1.f / t;
    }
    __syncthreads();
    const float inv = bcast;
    union { __half2 h2[2]; uint2 u; } pa, pb;
    pa.h2[0] = __floats2half2_rn(va.x * inv, va.y * inv);
    pa.h2[1] = __floats2half2_rn(va.z * inv, va.w * inv);
    pb.h2[0] = __floats2half2_rn(vb.x * inv, vb.y * inv);
    pb.h2[1] = __floats2half2_rn(vb.z * inv, vb.w * inv);
    *(uint2*)&O[tid * 4]         = pa.u;
    *(uint2*)&O[(tid + 288) * 4] = pb.u;
}

// ---------------------------------------------------------------------------
extern "C" void kernel_launch(void* const* d_in, const int* in_sizes, int n_in,
                              void* d_out, int out_size)
{
    const float* L  = (const float*)d_in[0];
    const float* R  = (const float*)d_in[1];
    const float* wq = (const float*)d_in[2];
    const float* bq = (const float*)d_in[3];
    const float* wr = (const float*)d_in[4];
    const float* br = (const float*)d_in[5];
    float* out = (float*)d_out;

    bf16 *xh, *xl, *wh, *wl, *qh, *ql, *kh, *kl;
    float* attn;
    __half *attn_h, *vh;
    cudaGetSymbolAddress((void**)&xh, g_xh);
    cudaGetSymbolAddress((void**)&xl, g_xl);
    cudaGetSymbolAddress((void**)&wh, g_wh);
    cudaGetSymbolAddress((void**)&wl, g_wl);
    cudaGetSymbolAddress((void**)&qh, g_qh);
    cudaGetSymbolAddress((void**)&ql, g_ql);
    cudaGetSymbolAddress((void**)&kh, g_kh);
    cudaGetSymbolAddress((void**)&kl, g_kl);
    cudaGetSymbolAddress((void**)&attn, g_attn);
    cudaGetSymbolAddress((void**)&attn_h, g_attn_h);
    cudaGetSymbolAddress((void**)&vh, g_vh);

    int nsm = 148;
    cudaDeviceGetAttribute(&nsm, cudaDevAttrMultiProcessorCount, 0);
    const int pgrid = 2 * nsm;

    const int pr_smem = 3 * PR_STAGE_B + 128;
    const int sc_smem = 3 * SC_STAGE_B + 128;
    const int av_smem = 3 * AV_STAGE_B + 128;
    cudaFuncSetAttribute(proj_bf16_kernel, cudaFuncAttributeMaxDynamicSharedMemorySize, pr_smem);
    cudaFuncSetAttribute(scores_bf16_kernel, cudaFuncAttributeMaxDynamicSharedMemorySize, sc_smem);
    cudaFuncSetAttribute(av_fp16_kernel, cudaFuncAttributeMaxDynamicSharedMemorySize, av_smem);

    split_w_kernel<<<2048, 256>>>(wq, wr, wh, wl);
    prep_kernel<<<dim3(NN / 64, CC / 64, 8), 256>>>(L, R, out, vh, xh, xl);
    proj_bf16_kernel<<<dim3(4, NN / 128, 8), 256, pr_smem>>>(
        xh, xl, wh, wl, bq, br, qh, ql, kh, kl);
    scores_bf16_kernel<<<pgrid, 256, sc_smem>>>(qh, ql, kh, kl, attn);
    softmax_kernel<<<2 * BB * NN, 288>>>(attn, attn_h);
    av_fp16_kernel<<<pgrid, 256, av_smem>>>(vh, attn_h, out);
}

// round 15
// speedup vs baseline: 1.0124x; 1.0124x over previous
#include <cuda_runtime.h>
#include <cuda_bf16.h>
#include <cuda_fp16.h>
#include <cstdint>

#define BB 4
#define CC 2048
#define NN 2304   // 48*48
#define DD 256

typedef __nv_bfloat16 bf16;
typedef __nv_bfloat162 bf162;

// ---------------------------------------------------------------------------
// Scratch (__device__ globals)
// ---------------------------------------------------------------------------
__device__ bf16 g_xh[2ull * BB * NN * CC];
__device__ bf16 g_xl[2ull * BB * NN * CC];
__device__ bf16 g_wh[2ull * DD * CC];
__device__ bf16 g_wl[2ull * DD * CC];
__device__ bf16 g_qh[2ull * BB * NN * DD];
__device__ bf16 g_ql[2ull * BB * NN * DD];
__device__ bf16 g_kh[2ull * BB * NN * DD];
__device__ bf16 g_kl[2ull * BB * NN * DD];
__device__ float g_attn[2ull * BB * NN * NN];    // fp32 scores
__device__ __half g_attn_h[2ull * BB * NN * NN]; // fp16 softmaxed attn
__device__ __half g_vh[2ull * BB * CC * NN];     // fp16 copies of L (src 0) and R (src 1)

// ---------------------------------------------------------------------------
// helpers
// ---------------------------------------------------------------------------
__device__ __forceinline__ uint32_t smem_u32(const void* p) {
    uint32_t a;
    asm("{ .reg .u64 t; cvta.to.shared.u64 t, %1; cvt.u32.u64 %0, t; }" : "=r"(a) : "l"(p));
    return a;
}

__device__ __forceinline__ void cp16(uint32_t dst, const void* src) {
    asm volatile("cp.async.cg.shared.global [%0], [%1], 16;" :: "r"(dst), "l"(src));
}
#define CP_COMMIT() asm volatile("cp.async.commit_group;")
#define CP_WAIT(n)  asm volatile("cp.async.wait_group %0;" :: "n"(n))

__device__ __forceinline__ void ldsm4(uint32_t* r, uint32_t addr) {
    asm volatile("ldmatrix.sync.aligned.m8n8.x4.shared.b16 {%0,%1,%2,%3}, [%4];"
        : "=r"(r[0]), "=r"(r[1]), "=r"(r[2]), "=r"(r[3]) : "r"(addr));
}

__device__ __forceinline__ void mma16(float* c, const uint32_t* a, const uint32_t* b) {
    asm volatile(
        "mma.sync.aligned.m16n8k16.row.col.f32.bf16.bf16.f32 "
        "{%0,%1,%2,%3}, {%4,%5,%6,%7}, {%8,%9}, {%0,%1,%2,%3};"
        : "+f"(c[0]), "+f"(c[1]), "+f"(c[2]), "+f"(c[3])
        : "r"(a[0]), "r"(a[1]), "r"(a[2]), "r"(a[3]), "r"(b[0]), "r"(b[1]));
}

__device__ __forceinline__ void mma16h(float* c, const uint32_t* a, const uint32_t* b) {
    asm volatile(
        "mma.sync.aligned.m16n8k16.row.col.f32.f16.f16.f32 "
        "{%0,%1,%2,%3}, {%4,%5,%6,%7}, {%8,%9}, {%0,%1,%2,%3};"
        : "+f"(c[0]), "+f"(c[1]), "+f"(c[2]), "+f"(c[3])
        : "r"(a[0]), "r"(a[1]), "r"(a[2]), "r"(a[3]), "r"(b[0]), "r"(b[1]));
}

__device__ __forceinline__ void split_bf(float v, bf16& h, bf16& l) {
    h = __float2bfloat16(v);
    l = __float2bfloat16(v - __bfloat162float(h));
}

// fast exp: exp2 poly (deg-6, rel err ~1.5e-5), no MUFU
__device__ __forceinline__ float fexp(float x) {
    float t = fmaxf(x * 1.44269504089f, -120.f);
    float fi = floorf(t);
    float f = t - fi;
    float p = 1.54953e-4f;
    p = fmaf(p, f, 0.00133335581f);
    p = fmaf(p, f, 0.00961812911f);
    p = fmaf(p, f, 0.0555041087f);
    p = fmaf(p, f, 0.240226507f);
    p = fmaf(p, f, 0.693147181f);
    p = fmaf(p, f, 1.0f);
    return __int_as_float(__float_as_int(p) + ((int)fi << 23));
}

// ===========================================================================
// prep: fused conv_copy + split_x + (z==8) split_w. Vectorized IO.
// z in [0,8): 64x64 (c,n) tile of L/R -> out halves + fp16 V + bf16 xh/xl.
// z == 8: blocks (x,y) flattened cover W split (2*DD*CC elements).
// grid (36, 32, 9)
// ===========================================================================
__global__ void __launch_bounds__(256) prep_kernel(
    const float* __restrict__ L, const float* __restrict__ R,
    const float* __restrict__ wq, const float* __restrict__ wr,
    float* __restrict__ out, __half* __restrict__ vh,
    bf16* __restrict__ xh, bf16* __restrict__ xl,
    bf16* __restrict__ wh, bf16* __restrict__ wl)
{
    __shared__ float t[64][65];
    const int z = blockIdx.z;

    if (z == 8) {
        // W split: 2*DD*CC = 1,048,576 floats -> 524,288 float2 units.
        // 36*32=1152 blocks x 256 threads = 294,912 threads; 2 units each.
        const int bidf = blockIdx.y * 36 + blockIdx.x;
        size_t base = (size_t)bidf * 256 + threadIdx.x;
        const size_t total2 = (size_t)2 * DD * CC / 2;
#pragma unroll
        for (int rep = 0; rep < 2; rep++) {
            size_t i = base + (size_t)rep * 294912;
            if (i < total2) {
                size_t p = i * 2;
                const float* src = (p < (size_t)DD * CC) ? wq + p : wr + (p - (size_t)DD * CC);
                float2 v = *(const float2*)src;
                bf16 h0, l0, h1, l1;
                split_bf(v.x, h0, l0);
                split_bf(v.y, h1, l1);
                *(bf162*)&wh[p] = bf162(h0, h1);
                *(bf162*)&wl[p] = bf162(l0, l1);
            }
        }
        return;
    }

    const int src = z >> 2, b = z & 3;
    const float* X = (src ? R : L) + (size_t)b * CC * NN;
    float* outp = out + (src ? (size_t)BB * 2 * CC * NN : 0) + (size_t)b * 2 * CC * NN;
    __half* vp = vh + (size_t)z * CC * NN;
    bf16* oh = xh + (size_t)z * NN * CC;
    bf16* ol = xl + (size_t)z * NN * CC;
    const int n0 = blockIdx.x << 6, c0 = blockIdx.y << 6;
    const int tid = threadIdx.x;

#pragma unroll
    for (int i = 0; i < 4; i++) {
        int idx = tid + (i << 8);
        int cc = idx >> 4;
        int n4 = (idx & 15) << 2;
        size_t go = (size_t)(c0 + cc) * NN + n0 + n4;
        float4 v = *(const float4*)(X + go);
        *(float4*)(outp + go) = v;
        union { __half2 h2[2]; uint2 u; } pv;
        pv.h2[0] = __floats2half2_rn(v.x, v.y);
        pv.h2[1] = __floats2half2_rn(v.z, v.w);
        *(uint2*)(vp + go) = pv.u;
        t[cc][n4 + 0] = v.x;
        t[cc][n4 + 1] = v.y;
        t[cc][n4 + 2] = v.z;
        t[cc][n4 + 3] = v.w;
    }
    __syncthreads();

    {
        const int n = tid >> 2;
        const int cg = (tid & 3) << 4;
        union { bf162 h2[8]; uint4 u4[2]; } ph, pl;
#pragma unroll
        for (int e = 0; e < 8; e++) {
            float v0 = t[cg + 2 * e][n], v1 = t[cg + 2 * e + 1][n];
            bf16 h0, l0, h1, l1;
            split_bf(v0, h0, l0);
            split_bf(v1, h1, l1);
            ph.h2[e] = bf162(h0, h1);
            pl.h2[e] = bf162(l0, l1);
        }
        size_t off = (size_t)(n0 + n) * CC + c0 + cg;
        *(uint4*)&oh[off]     = ph.u4[0];
        *(uint4*)&oh[off + 8] = ph.u4[1];
        *(uint4*)&ol[off]     = pl.u4[0];
        *(uint4*)&ol[off + 8] = pl.u4[1];
    }
}

// ===========================================================================
// proj (bf16x3, ldmatrix + swizzle, 2 CTAs/SM — R13/R12 proven config)
// ===========================================================================
#define PR_STAGE_B 32768

__global__ void __launch_bounds__(256, 2) proj_bf16_kernel(
    const bf16* __restrict__ xh, const bf16* __restrict__ xl,
    const bf16* __restrict__ whg, const bf16* __restrict__ wlg,
    const float* __restrict__ bq, const float* __restrict__ br,
    bf16* __restrict__ qh_g, bf16* __restrict__ ql_g,
    bf16* __restrict__ kh_g, bf16* __restrict__ kl_g)
{
    extern __shared__ char prsm[];
    const int x = blockIdx.x >> 1;
    const int d0 = (blockIdx.x & 1) << 7;
    const int z = blockIdx.z, src = z >> 2, b = z & 3;
    const bf16* Xh = xh + (size_t)z * NN * CC;
    const bf16* Xl = xl + (size_t)z * NN * CC;
    const bf16* Wh = whg + (size_t)x * DD * CC + (size_t)d0 * CC;
    const bf16* Wl = wlg + (size_t)x * DD * CC + (size_t)d0 * CC;
    const float* bias = x ? br : bq;
    const int dir = x ? (src ^ 1) : src;
    bf16* oh = (x ? kh_g : qh_g) + ((size_t)dir * BB + b) * NN * DD;
    bf16* ol = (x ? kl_g : ql_g) + ((size_t)dir * BB + b) * NN * DD;
    const int m0 = blockIdx.y << 7;

    const uint32_t ab = (smem_u32(prsm) + 127) & ~127u;

    const int tid = threadIdx.x, wid = tid >> 5, lane = tid & 31;
    const int wm = wid >> 1, wn = wid & 1;
    const int gid = lane >> 2, tig = lane & 3;
    const int li = lane >> 3, lj = lane & 7;
    const int swj = lj >> 1;

    float acc[2][8][4];
#pragma unroll
    for (int i = 0; i < 2; i++)
#pragma unroll
        for (int j = 0; j < 8; j++)
#pragma unroll
            for (int e = 0; e < 4; e++) acc[i][j][e] = 0.f;

    auto load_tile = [&](int s, int kt) {
        const uint32_t st = ab + (uint32_t)s * PR_STAGE_B;
        const int kb = kt << 5;
#pragma unroll
        for (int i = 0; i < 2; i++) {
            int idx = tid + (i << 8);
            int row = idx >> 2, g = idx & 3;
            uint32_t off = row * 64 + 16 * (g ^ ((row >> 1) & 3));
            cp16(st + off,         Xh + (size_t)(m0 + row) * CC + kb + g * 8);
            cp16(st + 8192 + off,  Xl + (size_t)(m0 + row) * CC + kb + g * 8);
            cp16(st + 16384 + off, Wh + (size_t)row * CC + kb + g * 8);
            cp16(st + 24576 + off, Wl + (size_t)row * CC + kb + g * 8);
        }
    };

    auto compute = [&](int s) {
        const uint32_t st = ab + (uint32_t)s * PR_STAGE_B;
        const uint32_t a_rb = ((wm << 5) + ((li & 1) << 3) + lj) * 64;
        const uint32_t b_rb = ((wn << 6) + ((li >> 1) << 3) + lj) * 64;
#pragma unroll
        for (int ks = 0; ks < 2; ks++) {
            const uint32_t xa = 16u * (((ks << 1) + (li >> 1)) ^ swj);
            const uint32_t xb = 16u * (((ks << 1) + (li & 1)) ^ swj);
            uint32_t ah[2][4], al[2][4];
#pragma unroll
            for (int mf = 0; mf < 2; mf++) {
                ldsm4(ah[mf], st + a_rb + mf * 1024 + xa);
                ldsm4(al[mf], st + 8192 + a_rb + mf * 1024 + xa);
            }
            uint32_t bh[4][4], bl[4][4];
#pragma unroll
            for (int nf2 = 0; nf2 < 4; nf2++) {
                ldsm4(bh[nf2], st + 16384 + b_rb + nf2 * 1024 + xb);
                ldsm4(bl[nf2], st + 24576 + b_rb + nf2 * 1024 + xb);
            }
#pragma unroll
            for (int mf = 0; mf < 2; mf++)
#pragma unroll
                for (int nf2 = 0; nf2 < 4; nf2++) {
                    mma16(acc[mf][2 * nf2],     ah[mf], &bh[nf2][0]);
                    mma16(acc[mf][2 * nf2],     ah[mf], &bl[nf2][0]);
                    mma16(acc[mf][2 * nf2],     al[mf], &bh[nf2][0]);
                    mma16(acc[mf][2 * nf2 + 1], ah[mf], &bh[nf2][2]);
                    mma16(acc[mf][2 * nf2 + 1], ah[mf], &bl[nf2][2]);
                    mma16(acc[mf][2 * nf2 + 1], al[mf], &bh[nf2][2]);
                }
        }
    };

    const int KT = CC >> 5;  // 64
    load_tile(0, 0); CP_COMMIT();
    load_tile(1, 1); CP_COMMIT();
    for (int kt = 0; kt < KT; kt++) {
        CP_WAIT(1);
        __syncthreads();
        compute(kt % 3);
        if (kt + 2 < KT) load_tile((kt + 2) % 3, kt + 2);
        CP_COMMIT();
    }

#pragma unroll
    for (int mf = 0; mf < 2; mf++) {
        const int r = m0 + (wm << 5) + (mf << 4) + gid;
#pragma unroll
        for (int nf = 0; nf < 8; nf++) {
            const int col = d0 + (wn << 6) + (nf << 3) + (tig << 1);
            const float b0 = bias[col], b1 = bias[col + 1];
            float v0 = acc[mf][nf][0] + b0, v1 = acc[mf][nf][1] + b1;
            float v2 = acc[mf][nf][2] + b0, v3 = acc[mf][nf][3] + b1;
            bf16 h0, l0, h1, l1, h2, l2, h3, l3;
            split_bf(v0, h0, l0); split_bf(v1, h1, l1);
            split_bf(v2, h2, l2); split_bf(v3, h3, l3);
            *(bf162*)&oh[(size_t)r * DD + col]       = bf162(h0, h1);
            *(bf162*)&oh[(size_t)(r + 8) * DD + col] = bf162(h2, h3);
            *(bf162*)&ol[(size_t)r * DD + col]       = bf162(l0, l1);
            *(bf162*)&ol[(size_t)(r + 8) * DD + col] = bf162(l2, l3);
        }
    }
}

// ===========================================================================
// scores (bf16x3, ldmatrix + swizzle, 2 CTAs/SM — R13/R12 proven config)
// ===========================================================================
#define SC_STAGE_B 32768

__global__ void __launch_bounds__(256, 2) scores_bf16_kernel(
    const bf16* __restrict__ qh_g, const bf16* __restrict__ ql_g,
    const bf16* __restrict__ kh_g, const bf16* __restrict__ kl_g,
    float* __restrict__ Sb)
{
    extern __shared__ char scsm[];
    const size_t z = blockIdx.z;
    const bf16* qh = qh_g + z * NN * DD;
    const bf16* ql = ql_g + z * NN * DD;
    const bf16* kh = kh_g + z * NN * DD;
    const bf16* kl = kl_g + z * NN * DD;
    float* S = Sb + z * NN * NN;
    const int i0 = blockIdx.y << 7;
    const int j0 = blockIdx.x << 7;

    const uint32_t ab = (smem_u32(scsm) + 127) & ~127u;

    const int tid = threadIdx.x, wid = tid >> 5, lane = tid & 31;
    const int wm = wid >> 1, wn = wid & 1;
    const int gid = lane >> 2, tig = lane & 3;
    const int li = lane >> 3, lj = lane & 7;
    const int swj = lj >> 1;

    float acc[2][8][4];
#pragma unroll
    for (int i = 0; i < 2; i++)
#pragma unroll
        for (int j = 0; j < 8; j++)
#pragma unroll
            for (int e = 0; e < 4; e++) acc[i][j][e] = 0.f;

    auto load_tile = [&](int s, int kt) {
        const uint32_t st = ab + (uint32_t)s * SC_STAGE_B;
        const int kb = kt << 5;
#pragma unroll
        for (int i = 0; i < 2; i++) {
            int idx = tid + (i << 8);
            int row = idx >> 2, g = idx & 3;
            uint32_t off = row * 64 + 16 * (g ^ ((row >> 1) & 3));
            cp16(st + off,         qh + (size_t)(i0 + row) * DD + kb + g * 8);
            cp16(st + 8192 + off,  ql + (size_t)(i0 + row) * DD + kb + g * 8);
            cp16(st + 16384 + off, kh + (size_t)(j0 + row) * DD + kb + g * 8);
            cp16(st + 24576 + off, kl + (size_t)(j0 + row) * DD + kb + g * 8);
        }
    };

    auto compute = [&](int s) {
        const uint32_t st = ab + (uint32_t)s * SC_STAGE_B;
        const uint32_t a_rb = ((wm << 5) + ((li & 1) << 3) + lj) * 64;
        const uint32_t b_rb = ((wn << 6) + ((li >> 1) << 3) + lj) * 64;
#pragma unroll
        for (int ks = 0; ks < 2; ks++) {
            const uint32_t xa = 16u * (((ks << 1) + (li >> 1)) ^ swj);
            const uint32_t xb = 16u * (((ks << 1) + (li & 1)) ^ swj);
            uint32_t ah[2][4], al[2][4];
#pragma unroll
            for (int mf = 0; mf < 2; mf++) {
                ldsm4(ah[mf], st + a_rb + mf * 1024 + xa);
                ldsm4(al[mf], st + 8192 + a_rb + mf * 1024 + xa);
            }
            uint32_t bh[4][4], bl[4][4];
#pragma unroll
            for (int nf2 = 0; nf2 < 4; nf2++) {
                ldsm4(bh[nf2], st + 16384 + b_rb + nf2 * 1024 + xb);
                ldsm4(bl[nf2], st + 24576 + b_rb + nf2 * 1024 + xb);
            }
#pragma unroll
            for (int mf = 0; mf < 2; mf++)
#pragma unroll
                for (int nf2 = 0; nf2 < 4; nf2++) {
                    mma16(acc[mf][2 * nf2],     ah[mf], &bh[nf2][0]);
                    mma16(acc[mf][2 * nf2],     ah[mf], &bl[nf2][0]);
                    mma16(acc[mf][2 * nf2],     al[mf], &bh[nf2][0]);
                    mma16(acc[mf][2 * nf2 + 1], ah[mf], &bh[nf2][2]);
                    mma16(acc[mf][2 * nf2 + 1], ah[mf], &bl[nf2][2]);
                    mma16(acc[mf][2 * nf2 + 1], al[mf], &bh[nf2][2]);
                }
        }
    };

    const int KT = DD >> 5;  // 8
    load_tile(0, 0); CP_COMMIT();
    load_tile(1, 1); CP_COMMIT();
    for (int kt = 0; kt < KT; kt++) {
        CP_WAIT(1);
        __syncthreads();
        compute(kt % 3);
        if (kt + 2 < KT) load_tile((kt + 2) % 3, kt + 2);
        CP_COMMIT();
    }

#pragma unroll
    for (int mf = 0; mf < 2; mf++) {
        const int r = i0 + (wm << 5) + (mf << 4) + gid;
#pragma unroll
        for (int nf = 0; nf < 8; nf++) {
            const int col = j0 + (wn << 6) + (nf << 3) + (tig << 1);
            *(float2*)&S[(size_t)r * NN + col]       = make_float2(acc[mf][nf][0], acc[mf][nf][1]);
            *(float2*)&S[(size_t)(r + 8) * NN + col] = make_float2(acc[mf][nf][2], acc[mf][nf][3]);
        }
    }
}

// ===========================================================================
// av: fp16 operands + ldsm prefetch (R13 proven config, 2 CTAs/SM)
// ===========================================================================
#define AV_STAGE_B 32768

__global__ void __launch_bounds__(256, 2) av_fp16_kernel(
    const __half* __restrict__ vhg, const __half* __restrict__ attnb,
    float* __restrict__ out)
{
    extern __shared__ char avsm[];
    const int z = blockIdx.z, dir = z >> 2, b = z & 3;
    const __half* V  = vhg + ((size_t)((dir ^ 1) * BB + b)) * CC * NN;
    const __half* At = attnb + (size_t)z * NN * NN;
    float* outb = out + ((size_t)(dir ? BB : 0) + b) * 2 * CC * NN + (size_t)CC * NN;
    const int c0r = blockIdx.y << 7;
    const int n0  = blockIdx.x << 7;

    const uint32_t ab = (smem_u32(avsm) + 127) & ~127u;

    const int tid = threadIdx.x, wid = tid >> 5, lane = tid & 31;
    const int wm = wid >> 1, wn = wid & 1;
    const int gid = lane >> 2, tig = lane & 3;
    const int li = lane >> 3, lj = lane & 7;

    float acc[2][8][4];
#pragma unroll
    for (int i = 0; i < 2; i++)
#pragma unroll
        for (int j = 0; j < 8; j++)
#pragma unroll
            for (int e = 0; e < 4; e++) acc[i][j][e] = 0.f;

    auto load_tile = [&](int s, int kt) {
        const uint32_t st = ab + (uint32_t)s * AV_STAGE_B;
        const int kb = kt << 6;
#pragma unroll
        for (int i = 0; i < 4; i++) {
            int idx = tid + (i << 8);
            int row = idx >> 3, g = idx & 7;
            uint32_t off = row * 128 + 16 * (g ^ (row & 7));
            cp16(st + off,         V  + (size_t)(c0r + row) * NN + kb + g * 8);
            cp16(st + 16384 + off, At + (size_t)(n0 + row) * NN + kb + g * 8);
        }
    };

    const uint32_t a_rb = ((wm << 5) + ((li & 1) << 3) + lj) * 128;
    const uint32_t b_rb = ((wn << 6) + ((li >> 1) << 3) + lj) * 128;

    auto ldfrag = [&](uint32_t st, int ks, uint32_t a[2][4], uint32_t bf[4][4]) {
        const uint32_t xa = 16u * (((ks << 1) + (li >> 1)) ^ lj);
        const uint32_t xb = 16u * (((ks << 1) + (li & 1)) ^ lj);
#pragma unroll
        for (int mf = 0; mf < 2; mf++)
            ldsm4(a[mf], st + a_rb + mf * 2048 + xa);
#pragma unroll
        for (int nf2 = 0; nf2 < 4; nf2++)
            ldsm4(bf[nf2], st + 16384 + b_rb + nf2 * 2048 + xb);
    };

    auto compute = [&](int s) {
        const uint32_t st = ab + (uint32_t)s * AV_STAGE_B;
        uint32_t a[2][2][4], bf[2][4][4];
        ldfrag(st, 0, a[0], bf[0]);
#pragma unroll
        for (int ks = 0; ks < 4; ks++) {   // 4 x k16 = k64
            const int cur = ks & 1, nxt = cur ^ 1;
            if (ks < 3) ldfrag(st, ks + 1, a[nxt], bf[nxt]);
#pragma unroll
            for (int mf = 0; mf < 2; mf++)
#pragma unroll
                for (int nf2 = 0; nf2 < 4; nf2++) {
                    mma16h(acc[mf][2 * nf2],     a[cur][mf], &bf[cur][nf2][0]);
                    mma16h(acc[mf][2 * nf2 + 1], a[cur][mf], &bf[cur][nf2][2]);
                }
        }
    };

    const int KT = NN >> 6;  // 36
    load_tile(0, 0); CP_COMMIT();
    load_tile(1, 1); CP_COMMIT();
    for (int kt = 0; kt < KT; kt++) {
        CP_WAIT(1);
        __syncthreads();
        compute(kt % 3);
        if (kt + 2 < KT) load_tile((kt + 2) % 3, kt + 2);
        CP_COMMIT();
    }

#pragma unroll
    for (int mf = 0; mf < 2; mf++) {
        const int r = c0r + (wm << 5) + (mf << 4) + gid;
#pragma unroll
        for (int nf = 0; nf < 8; nf++) {
            const int col = n0 + (wn << 6) + (nf << 3) + (tig << 1);
            *(float2*)&outb[(size_t)r * NN + col]       = make_float2(acc[mf][nf][0], acc[mf][nf][1]);
            *(float2*)&outb[(size_t)(r + 8) * NN + col] = make_float2(acc[mf][nf][2], acc[mf][nf][3]);
        }
    }
}

// ===========================================================================
// softmax: reads fp32 scores, writes fp16 attn (unchanged)
// ===========================================================================
__global__ void __launch_bounds__(288) softmax_kernel(
    const float* __restrict__ Sb, __half* __restrict__ Ob)
{
    const float4* S4 = (const float4*)(Sb + (size_t)blockIdx.x * NN);
    __half* O = Ob + (size_t)blockIdx.x * NN;
    const int tid = threadIdx.x;
    __shared__ float red[9];
    __shared__ float bcast;

    float4 va = S4[tid], vb = S4[tid + 288];
    float m = fmaxf(fmaxf(fmaxf(va.x, va.y), fmaxf(va.z, va.w)),
                    fmaxf(fmaxf(vb.x, vb.y), fmaxf(vb.z, vb.w)));
#pragma unroll
    for (int o = 16; o; o >>= 1) m = fmaxf(m, __shfl_xor_sync(0xffffffffu, m, o));
    if ((tid & 31) == 0) red[tid >> 5] = m;
    __syncthreads();
    if (tid == 0) {
        float t = red[0];
#pragma unroll
        for (int i = 1; i < 9; i++) t = fmaxf(t, red[i]);
        bcast = t;
    }
    __syncthreads();
    m = bcast;

    va.x = fexp(va.x - m); va.y = fexp(va.y - m);
    va.z = fexp(va.z - m); va.w = fexp(va.w - m);
    vb.x = fexp(vb.x - m); vb.y = fexp(vb.y - m);
    vb.z = fexp(vb.z - m); vb.w = fexp(vb.w - m);
    float s = va.x + va.y + va.z + va.w + vb.x + vb.y + vb.z + vb.w;
#pragma unroll
    for (int o = 16; o; o >>= 1) s += __shfl_xor_sync(0xffffffffu, s, o);
    __syncthreads();
    if ((tid & 31) == 0) red[tid >> 5] = s;
    __syncthreads();
    if (tid == 0) {
        float t = 0.f;
#pragma unroll
        for (int i = 0; i < 9; i++) t += red[i];
        bcast = 1.f / t;
    }
    __syncthreads();
    const float inv = bcast;
    union { __half2 h2[2]; uint2 u; } pa, pb;
    pa.h2[0] = __floats2half2_rn(va.x * inv, va.y * inv);
    pa.h2[1] = __floats2half2_rn(va.z * inv, va.w * inv);
    pb.h2[0] = __floats2half2_rn(vb.x * inv, vb.y * inv);
    pb.h2[1] = __floats2half2_rn(vb.z * inv, vb.w * inv);
    *(uint2*)&O[tid * 4]         = pa.u;
    *(uint2*)&O[(tid + 288) * 4] = pb.u;
}

// ---------------------------------------------------------------------------
extern "C" void kernel_launch(void* const* d_in, const int* in_sizes, int n_in,
                              void* d_out, int out_size)
{
    const float* L  = (const float*)d_in[0];
    const float* R  = (const float*)d_in[1];
    const float* wq = (const float*)d_in[2];
    const float* bq = (const float*)d_in[3];
    const float* wr = (const float*)d_in[4];
    const float* br = (const float*)d_in[5];
    float* out = (float*)d_out;

    bf16 *xh, *xl, *wh, *wl, *qh, *ql, *kh, *kl;
    float* attn;
    __half *attn_h, *vh;
    cudaGetSymbolAddress((void**)&xh, g_xh);
    cudaGetSymbolAddress((void**)&xl, g_xl);
    cudaGetSymbolAddress((void**)&wh, g_wh);
    cudaGetSymbolAddress((void**)&wl, g_wl);
    cudaGetSymbolAddress((void**)&qh, g_qh);
    cudaGetSymbolAddress((void**)&ql, g_ql);
    cudaGetSymbolAddress((void**)&kh, g_kh);
    cudaGetSymbolAddress((void**)&kl, g_kl);
    cudaGetSymbolAddress((void**)&attn, g_attn);
    cudaGetSymbolAddress((void**)&attn_h, g_attn_h);
    cudaGetSymbolAddress((void**)&vh, g_vh);

    const int pr_smem = 3 * PR_STAGE_B + 128;
    const int sc_smem = 3 * SC_STAGE_B + 128;
    const int av_smem = 3 * AV_STAGE_B + 128;
    cudaFuncSetAttribute(proj_bf16_kernel, cudaFuncAttributeMaxDynamicSharedMemorySize, pr_smem);
    cudaFuncSetAttribute(scores_bf16_kernel, cudaFuncAttributeMaxDynamicSharedMemorySize, sc_smem);
    cudaFuncSetAttribute(av_fp16_kernel, cudaFuncAttributeMaxDynamicSharedMemorySize, av_smem);

    prep_kernel<<<dim3(NN / 64, CC / 64, 9), 256>>>(L, R, wq, wr, out, vh, xh, xl, wh, wl);
    proj_bf16_kernel<<<dim3(4, NN / 128, 8), 256, pr_smem>>>(
        xh, xl, wh, wl, bq, br, qh, ql, kh, kl);
    scores_bf16_kernel<<<dim3(NN / 128, NN / 128, 8), 256, sc_smem>>>(qh, ql, kh, kl, attn);
    softmax_kernel<<<2 * BB * NN, 288>>>(attn, attn_h);
    av_fp16_kernel<<<dim3(NN / 128, CC / 128, 8), 256, av_smem>>>(vh, attn_h, out);
}